// round 16
// baseline (speedup 1.0000x reference)
#include <cuda_runtime.h>
#include <cuda_fp16.h>
#include <math.h>
#include <stdint.h>

// Problem constants
#define B_    4
#define C_    384
#define C3_   1152
#define CT_   1536        // 1152 qkv + 384 bs
#define HH_   128
#define WW_   128
#define P_    16384       // H*W
#define HEADS_ 8
#define CH_   48
#define BH_   32          // B*HEADS
#define SPLITS_ 32
#define SCALE_ 0.14433756729740643f  // 1/sqrt(48)

#define LDK 40            // padded K stride (halfs) in A smem tiles
#define LDP 136           // padded P stride (halfs) in B smem tiles

// Scratch (static device arrays; no cudaMalloc allowed)
__device__ __align__(256) __half g_pwh[(size_t)B_ * CT_ * P_];  // pointwise out (fp16)
__device__ __align__(256) __half g_dwh[(size_t)B_ * CT_ * P_];  // depthwise out (fp16)
__device__ __align__(256) __half g_xc[(size_t)B_ * C_ * P_];    // x fp16 [b][c][p]
__device__ float g_part[(size_t)BH_ * SPLITS_ * CH_ * CH_];
__device__ float g_npart[(size_t)B_ * 2 * C_ * 4];  // per-block sumsq partials
__device__ float g_attn[(size_t)BH_ * CH_ * CH_];
// fp16 weights
__device__ __align__(256) __half g_wA[(size_t)CT_ * C_];          // [m][k]
__device__ __align__(256) __half g_wPb[(size_t)B_ * C_ * 2 * C_]; // fused proj W per batch

// ---------------------------------------------------------------------------
// Helpers
// ---------------------------------------------------------------------------
__device__ __forceinline__ uint32_t smem_u32(const void* p) {
    uint32_t a;
    asm("{ .reg .u64 t; cvta.to.shared.u64 t, %1; cvt.u32.u64 %0, t; }"
        : "=r"(a) : "l"(p));
    return a;
}
__device__ __forceinline__ void cp16(uint32_t sa, const void* g) {
    asm volatile("cp.async.cg.shared.global [%0], [%1], 16;" :: "r"(sa), "l"(g));
}
#define CP_COMMIT() asm volatile("cp.async.commit_group;" ::: "memory")
#define CP_WAIT0()  asm volatile("cp.async.wait_group 0;" ::: "memory")

__device__ __forceinline__ void ldm_x4(uint32_t* r, uint32_t addr) {
    asm volatile("ldmatrix.sync.aligned.m8n8.x4.shared.b16 {%0,%1,%2,%3}, [%4];"
        : "=r"(r[0]), "=r"(r[1]), "=r"(r[2]), "=r"(r[3]) : "r"(addr));
}
__device__ __forceinline__ void ldm_x4_t(uint32_t* r, uint32_t addr) {
    asm volatile("ldmatrix.sync.aligned.m8n8.x4.trans.shared.b16 {%0,%1,%2,%3}, [%4];"
        : "=r"(r[0]), "=r"(r[1]), "=r"(r[2]), "=r"(r[3]) : "r"(addr));
}
__device__ __forceinline__ void mma16816(float* c, const uint32_t* a, const uint32_t* b) {
    asm volatile("mma.sync.aligned.m16n8k16.row.col.f32.f16.f16.f32 "
        "{%0,%1,%2,%3}, {%4,%5,%6,%7}, {%8,%9}, {%0,%1,%2,%3};"
        : "+f"(c[0]), "+f"(c[1]), "+f"(c[2]), "+f"(c[3])
        : "r"(a[0]), "r"(a[1]), "r"(a[2]), "r"(a[3]), "r"(b[0]), "r"(b[1]));
}

__device__ __forceinline__ uint32_t pack_h(__half a, __half b) {
    return (uint32_t)__half_as_ushort(a) | ((uint32_t)__half_as_ushort(b) << 16);
}

// ---------------------------------------------------------------------------
// Combined convert kernel:
//   blocks [0, NXB)            : x fp32 -> fp16 elementwise (8 per thread)
//   blocks [NXB, NXB+NWB)      : g_wA + y-half of g_wPb weight converts
// ---------------------------------------------------------------------------
#define NXB ((int)(((size_t)B_ * C_ * P_) / (256 * 8)))   // 12288
#define NWB (((CT_ * C_ + C_ * 2 * C_) + 255) / 256)      // 3456

__global__ __launch_bounds__(256) void conv_all_kernel(
    const float* __restrict__ x,
    const float* __restrict__ w_qkv,
    const float* __restrict__ w_bs_pw,
    const float* __restrict__ w_proj)
{
    if (blockIdx.x < NXB) {
        size_t i = ((size_t)blockIdx.x * 256 + threadIdx.x) * 8;
        float4 a = *(const float4*)(x + i);
        float4 c = *(const float4*)(x + i + 4);
        uint4 o;
        o.x = pack_h(__float2half(a.x), __float2half(a.y));
        o.y = pack_h(__float2half(a.z), __float2half(a.w));
        o.z = pack_h(__float2half(c.x), __float2half(c.y));
        o.w = pack_h(__float2half(c.z), __float2half(c.w));
        *(uint4*)(g_xc + i) = o;
    } else {
        const int nA = CT_ * C_;       // 589824
        const int nP = C_ * 2 * C_;    // 294912
        int idx = (blockIdx.x - NXB) * 256 + threadIdx.x;
        if (idx < nA) {
            int m = idx / C_, k = idx % C_;
            float v = (m < C3_) ? w_qkv[m * C_ + k] : w_bs_pw[(m - C3_) * C_ + k];
            g_wA[idx] = __float2half(v);
        } else if (idx < nA + nP) {
            int j = idx - nA;
            int k = j % (2 * C_);
            if (k >= C_) {
                __half hv = __float2half(w_proj[j]);
                #pragma unroll
                for (int b = 0; b < B_; b++)
                    g_wPb[(size_t)b * C_ * 2 * C_ + j] = hv;
            }
        }
    }
}

// ---------------------------------------------------------------------------
// Fused proj weight, attn half: W'[b][m][h*48+d] = sum_d' Wp[m][h*48+d']*A[bh][d'][d]
// grid (BH, 6), 256 threads: each block 64 m-rows x 48 cols
// ---------------------------------------------------------------------------
__global__ __launch_bounds__(256) void wprime_kernel(const float* __restrict__ w_proj)
{
    __shared__ float A[CH_][CH_];
    const int bh = blockIdx.x;
    const int b = bh >> 3, h = bh & 7;
    const int m0 = blockIdx.y * 64;
    const int tid = threadIdx.x;

    for (int i = tid; i < CH_ * CH_; i += 256)
        A[i / CH_][i % CH_] = g_attn[(size_t)bh * CH_ * CH_ + i];
    __syncthreads();

    #pragma unroll
    for (int e = 0; e < 12; e++) {
        int idx = tid + e * 256;           // 0..3071
        int mr = idx / CH_;
        int d  = idx % CH_;
        int m  = m0 + mr;
        const float* wrow = w_proj + (size_t)m * (2 * C_) + h * CH_;
        float s = 0.f;
        #pragma unroll 8
        for (int dp = 0; dp < CH_; dp++)
            s += wrow[dp] * A[dp][d];
        g_wPb[((size_t)b * C_ + m) * (2 * C_) + h * CH_ + d] = __float2half(s);
    }
}

// ---------------------------------------------------------------------------
// HMMA GEMM, pure fp16, B consumed in [k][p] layout via ldmatrix.trans.
// MODE 0: pw  (A=g_wA,     B=g_xc,               out g_pwh fp16)
// MODE 1: proj(A=g_wPb[b], B=g_dwh ch 768..1535, out d_out fp32)
// ---------------------------------------------------------------------------
#define ATILE_BYTES (128 * LDK * 2)         // 10240
#define BTILE_BYTES (32 * LDP * 2)          // 8704
#define STAGE_BYTES (ATILE_BYTES + BTILE_BYTES) // 18944
#define GEMM_SMEM (2 * STAGE_BYTES)         // 37888

template <int MODE>
__global__ __launch_bounds__(256) void gemm_mma_kernel(void* __restrict__ outp_v)
{
    extern __shared__ __align__(16) char S[];
    const int Kdim = (MODE == 0) ? C_ : 2 * C_;
    const int Mdim = (MODE == 0) ? CT_ : C_;
    const int b  = blockIdx.z;
    const int n0 = blockIdx.x * 128;
    const int m0 = blockIdx.y * 128;

    const __half* Ap = (MODE == 0) ? g_wA
                                   : g_wPb + (size_t)b * C_ * 2 * C_;
    const __half* Bbase = (MODE == 0)
        ? g_xc + (size_t)b * C_ * P_
        : g_dwh + ((size_t)b * CT_ + 2 * C_) * P_;   // V (384) then y (384)

    const int tid  = threadIdx.x;
    const int lane = tid & 31, warp = tid >> 5;
    const int wm = warp >> 1, wn = warp & 1;
    const uint32_t sbase = smem_u32(S);

    float acc[2][8][4];
    #pragma unroll
    for (int mt = 0; mt < 2; mt++)
        #pragma unroll
        for (int nt = 0; nt < 8; nt++)
            #pragma unroll
            for (int q = 0; q < 4; q++) acc[mt][nt][q] = 0.f;

    const int nch = Kdim / 32;

    // ---- prologue load (stage 0, chunk 0): A 512 + B 512 16B-chunks
    {
        #pragma unroll
        for (int e = 0; e < 4; e++) {
            int idx = tid + e * 256;
            if (idx < 512) {
                int r = idx >> 2, sg = idx & 3;
                uint32_t sa = sbase + (r * LDK + sg * 8) * 2;
                cp16(sa, Ap + (size_t)(m0 + r) * Kdim + sg * 8);
            } else {
                int j2 = idx - 512;
                int r = j2 >> 4, sg = j2 & 15;
                uint32_t sa = sbase + ATILE_BYTES + (r * LDP + sg * 8) * 2;
                cp16(sa, Bbase + (size_t)r * P_ + n0 + sg * 8);
            }
        }
        CP_COMMIT();
    }

    for (int c = 0; c < nch; c++) {
        CP_WAIT0();
        __syncthreads();

        if (c + 1 < nch) {
            int k0 = (c + 1) * 32;
            uint32_t stg = sbase + ((c + 1) & 1) * STAGE_BYTES;
            #pragma unroll
            for (int e = 0; e < 4; e++) {
                int idx = tid + e * 256;
                if (idx < 512) {
                    int r = idx >> 2, sg = idx & 3;
                    uint32_t sa = stg + (r * LDK + sg * 8) * 2;
                    cp16(sa, Ap + (size_t)(m0 + r) * Kdim + k0 + sg * 8);
                } else {
                    int j2 = idx - 512;
                    int r = j2 >> 4, sg = j2 & 15;
                    uint32_t sa = stg + ATILE_BYTES + (r * LDP + sg * 8) * 2;
                    cp16(sa, Bbase + (size_t)(k0 + r) * P_ + n0 + sg * 8);
                }
            }
            CP_COMMIT();
        }

        // ---- compute on stage c&1
        const uint32_t stb = sbase + (c & 1) * STAGE_BYTES;
        const uint32_t bA = stb;
        const uint32_t bB = stb + ATILE_BYTES;

        #pragma unroll
        for (int kk = 0; kk < 2; kk++) {
            // A (row-major [m][k], non-trans)
            const int kA = kk * 16 + (lane >> 4) * 8;
            const int ar = wm * 32 + (lane & 15);
            uint32_t amat[2][4];
            #pragma unroll
            for (int mt = 0; mt < 2; mt++)
                ldm_x4(amat[mt], bA + ((ar + mt * 16) * LDK + kA) * 2);

            // B ([k][p] layout, trans ldmatrix)
            const int krow = kk * 16 + (lane & 7) + ((lane >> 4) << 3);
            const int ncol = ((lane >> 3) & 1) << 3;
            uint32_t bmat[8][2];
            #pragma unroll
            for (int nt2 = 0; nt2 < 4; nt2++) {
                const int nb = wn * 64 + nt2 * 16;
                uint32_t r[4];
                ldm_x4_t(r, bB + (krow * LDP + nb + ncol) * 2);
                bmat[nt2 * 2][0] = r[0]; bmat[nt2 * 2 + 1][0] = r[1];
                bmat[nt2 * 2][1] = r[2]; bmat[nt2 * 2 + 1][1] = r[3];
            }
            #pragma unroll
            for (int mt = 0; mt < 2; mt++)
                #pragma unroll
                for (int nt = 0; nt < 8; nt++)
                    mma16816(acc[mt][nt], amat[mt], bmat[nt]);
        }
        __syncthreads();
    }

    // ---- epilogue
    if (MODE == 0) {
        __half* outb = g_pwh + (size_t)b * Mdim * P_;
        #pragma unroll
        for (int mt = 0; mt < 2; mt++) {
            int r1 = m0 + wm * 32 + mt * 16 + (lane >> 2);
            #pragma unroll
            for (int nt = 0; nt < 8; nt++) {
                int col = n0 + wn * 64 + nt * 8 + 2 * (lane & 3);
                uint32_t v0 = pack_h(__float2half(acc[mt][nt][0]),
                                     __float2half(acc[mt][nt][1]));
                uint32_t v1 = pack_h(__float2half(acc[mt][nt][2]),
                                     __float2half(acc[mt][nt][3]));
                *(uint32_t*)&outb[(size_t)r1 * P_ + col]       = v0;
                *(uint32_t*)&outb[(size_t)(r1 + 8) * P_ + col] = v1;
            }
        }
    } else {
        float* outb = (float*)outp_v + (size_t)b * Mdim * P_;
        #pragma unroll
        for (int mt = 0; mt < 2; mt++) {
            int r1 = m0 + wm * 32 + mt * 16 + (lane >> 2);
            #pragma unroll
            for (int nt = 0; nt < 8; nt++) {
                int col = n0 + wn * 64 + nt * 8 + 2 * (lane & 3);
                *(float2*)&outb[(size_t)r1 * P_ + col] =
                    make_float2(acc[mt][nt][0], acc[mt][nt][1]);
                *(float2*)&outb[(size_t)(r1 + 8) * P_ + col] =
                    make_float2(acc[mt][nt][2], acc[mt][nt][3]);
            }
        }
    }
}

// ---------------------------------------------------------------------------
// Depthwise 3x3 conv (pad 1) + exact GELU on bs channels.
// fp16 in (uint4 loads) / fp16 out (packed STG.64). 32-row y-tiles (34 halo).
// Each thread: 4-wide x-quad over 2 output rows per half-tile (2 halves).
// Fused q/k sumsq partials. grid (HH/32, CT, B), 256 threads.
// ---------------------------------------------------------------------------
__global__ __launch_bounds__(256) void dw_kernel(
    const float* __restrict__ w_dw,
    const float* __restrict__ w_bs_dw)
{
    __shared__ float s[34][132];
    __shared__ float red[8];
    const int y0 = blockIdx.x * 32;
    const int ch = blockIdx.y;
    const int b  = blockIdx.z;
    const int tid = threadIdx.x;

    const __half* in = g_pwh + ((size_t)b * CT_ + ch) * P_;
    // 34 rows x 16 uint4 (8 halves) = 544 vector loads
    #pragma unroll
    for (int e = 0; e < 3; e++) {
        int idx = tid + e * 256;
        if (idx < 544) {
            int row = idx >> 4;
            int cg  = (idx & 15) * 8;
            int y = y0 - 1 + row;
            float f[8];
            if (y >= 0 && y < HH_) {
                uint4 u = *(const uint4*)(in + y * WW_ + cg);
                const __half2* h2 = (const __half2*)&u;
                #pragma unroll
                for (int q = 0; q < 4; q++) {
                    float2 v = __half22float2(h2[q]);
                    f[2 * q] = v.x; f[2 * q + 1] = v.y;
                }
            } else {
                #pragma unroll
                for (int q = 0; q < 8; q++) f[q] = 0.f;
            }
            #pragma unroll
            for (int q = 0; q < 8; q++) s[row][cg + 1 + q] = f[q];
        }
    }
    if (tid < 68) s[tid >> 1][(tid & 1) * 129] = 0.f;
    __syncthreads();

    const float* wp = (ch < C3_) ? (w_dw + ch * 9) : (w_bs_dw + (ch - C3_) * 9);
    float w[9];
    #pragma unroll
    for (int i = 0; i < 9; i++) w[i] = __ldg(&wp[i]);

    const int x0 = (tid & 31) * 4;     // quad start (phys cols x0..x0+5)
    const int rg = tid >> 5;           // 0..7
    const bool isqk = (ch < 2 * C_);
    const bool isbs = (ch >= C3_);
    __half* outc = g_dwh + ((size_t)b * CT_ + ch) * P_;

    float sumsq = 0.f;
    #pragma unroll
    for (int half = 0; half < 2; half++) {
        const int rb = half * 16 + rg * 2;   // smem top row for this 2-row group

        float rv[4][6];
        #pragma unroll
        for (int r = 0; r < 4; r++) {
            float4 v4 = *(const float4*)&s[rb + r][x0];
            float2 v2 = *(const float2*)&s[rb + r][x0 + 4];
            rv[r][0] = v4.x; rv[r][1] = v4.y; rv[r][2] = v4.z; rv[r][3] = v4.w;
            rv[r][4] = v2.x; rv[r][5] = v2.y;
        }

        #pragma unroll
        for (int j = 0; j < 2; j++) {
            const float* q0 = rv[j];
            const float* q1 = rv[j + 1];
            const float* q2 = rv[j + 2];
            uint32_t ph[2];
            #pragma unroll
            for (int pairi = 0; pairi < 2; pairi++) {
                __half hh[2];
                #pragma unroll
                for (int ii = 0; ii < 2; ii++) {
                    int i = pairi * 2 + ii;
                    float acc = w[0] * q0[i] + w[1] * q0[i + 1] + w[2] * q0[i + 2]
                              + w[3] * q1[i] + w[4] * q1[i + 1] + w[5] * q1[i + 2]
                              + w[6] * q2[i] + w[7] * q2[i + 1] + w[8] * q2[i + 2];
                    if (isbs)
                        acc = 0.5f * acc * (1.0f + erff(acc * 0.70710678118654752f));
                    hh[ii] = __float2half(acc);
                    if (isqk) {
                        float fv = __half2float(hh[ii]);
                        sumsq += fv * fv;
                    }
                }
                ph[pairi] = pack_h(hh[0], hh[1]);
            }
            *(uint2*)&outc[(y0 + rb + j) * WW_ + x0] = make_uint2(ph[0], ph[1]);
        }
    }

    if (isqk) {
        #pragma unroll
        for (int off = 16; off > 0; off >>= 1)
            sumsq += __shfl_xor_sync(0xFFFFFFFFu, sumsq, off);
        if ((tid & 31) == 0) red[tid >> 5] = sumsq;
        __syncthreads();
        if (tid == 0) {
            float t = red[0];
            #pragma unroll
            for (int q = 1; q < 8; q++) t += red[q];
            g_npart[(((size_t)b * 2 * C_ + ch) << 2) + blockIdx.x] = t;
        }
    }
}

// ---------------------------------------------------------------------------
// Attention logits split-K partials via HMMA: S_part = q[48,512] @ k[48,512]^T
// grid (SPLITS=32, BH=32), 128 threads (4 warps, each a K-32 slice per chunk)
// ---------------------------------------------------------------------------
__global__ __launch_bounds__(128) void attn_hmma_kernel()
{
    __shared__ __align__(16) float rbuf[4 * CH_ * CH_];
    __half* qs = (__half*)rbuf;                  // [48][136]
    __half* ks = (__half*)rbuf + 48 * 136;

    const int s  = blockIdx.x;
    const int bh = blockIdx.y;
    const int b = bh >> 3, h = bh & 7;
    const __half* qb = g_dwh + ((size_t)b * CT_ + h * CH_) * P_ + s * 512;
    const __half* kb = g_dwh + ((size_t)b * CT_ + C_ + h * CH_) * P_ + s * 512;

    const int tid = threadIdx.x;
    const int lane = tid & 31, warp = tid >> 5;
    const uint32_t sq = smem_u32(qs), sk = smem_u32(ks);

    float acc[3][6][4];
    #pragma unroll
    for (int mt = 0; mt < 3; mt++)
        #pragma unroll
        for (int nt = 0; nt < 6; nt++)
            #pragma unroll
            for (int q = 0; q < 4; q++) acc[mt][nt][q] = 0.f;

    for (int c0 = 0; c0 < 512; c0 += 128) {
        __syncthreads();
        #pragma unroll
        for (int e = 0; e < 6; e++) {
            int idx = tid + e * 128;       // 0..767
            int row = idx >> 4;
            int cg  = idx & 15;
            *(uint4*)(qs + row * 136 + cg * 8) =
                *(const uint4*)(qb + (size_t)row * P_ + c0 + cg * 8);
            *(uint4*)(ks + row * 136 + cg * 8) =
                *(const uint4*)(kb + (size_t)row * P_ + c0 + cg * 8);
        }
        __syncthreads();

        #pragma unroll
        for (int kk = 0; kk < 2; kk++) {
            const int ko = warp * 32 + kk * 16 + (lane >> 4) * 8;
            uint32_t amat[3][4];
            #pragma unroll
            for (int mt = 0; mt < 3; mt++)
                ldm_x4(amat[mt], sq + ((mt * 16 + (lane & 15)) * 136 + ko) * 2);
            uint32_t bmat[6][2];
            #pragma unroll
            for (int g2 = 0; g2 < 3; g2++) {
                uint32_t r[4];
                ldm_x4(r, sk + ((g2 * 16 + (lane & 15)) * 136 + ko) * 2);
                bmat[g2 * 2][0] = r[0]; bmat[g2 * 2 + 1][0] = r[1];
                bmat[g2 * 2][1] = r[2]; bmat[g2 * 2 + 1][1] = r[3];
            }
            #pragma unroll
            for (int mt = 0; mt < 3; mt++)
                #pragma unroll
                for (int nt = 0; nt < 6; nt++)
                    mma16816(acc[mt][nt], amat[mt], bmat[nt]);
        }
    }
    __syncthreads();

    float* rw = rbuf + warp * (CH_ * CH_);
    #pragma unroll
    for (int mt = 0; mt < 3; mt++)
        #pragma unroll
        for (int nt = 0; nt < 6; nt++) {
            int row = mt * 16 + (lane >> 2);
            int col = nt * 8 + (lane & 3) * 2;
            rw[row * CH_ + col]           = acc[mt][nt][0];
            rw[row * CH_ + col + 1]       = acc[mt][nt][1];
            rw[(row + 8) * CH_ + col]     = acc[mt][nt][2];
            rw[(row + 8) * CH_ + col + 1] = acc[mt][nt][3];
        }
    __syncthreads();

    float* out = g_part + ((size_t)bh * SPLITS_ + s) * (CH_ * CH_);
    for (int i = tid; i < CH_ * CH_; i += 128)
        out[i] = rbuf[i] + rbuf[CH_ * CH_ + i]
               + rbuf[2 * CH_ * CH_ + i] + rbuf[3 * CH_ * CH_ + i];
}

// ---------------------------------------------------------------------------
// Softmax rows; norms computed inline from g_npart partials.
// grid (CH, BH), 64 threads
// ---------------------------------------------------------------------------
__device__ __forceinline__ float norm_of(int b, int ch) {
    const float* p = g_npart + (((size_t)b * 2 * C_ + ch) << 2);
    return fmaxf(sqrtf(p[0] + p[1] + p[2] + p[3]), 1e-12f);
}

__global__ __launch_bounds__(64) void softmax_kernel()
{
    const int i  = blockIdx.x;
    const int bh = blockIdx.y;
    const int b = bh >> 3, h = bh & 7;
    const int j = threadIdx.x;

    float val = 0.f;
    float logit = -1e30f;
    if (j < CH_) {
        float sum = 0.f;
        #pragma unroll
        for (int s = 0; s < SPLITS_; s++)
            sum += g_part[((size_t)bh * SPLITS_ + s) * (CH_ * CH_) + i * CH_ + j];
        float nq = norm_of(b, h * CH_ + i);
        float nk = norm_of(b, C_ + h * CH_ + j);
        val = sum / (nq * nk) * SCALE_;
        logit = val;
    }
    __shared__ float red[64];
    red[j] = logit;
    __syncthreads();
    for (int off = 32; off > 0; off >>= 1) {
        if (j < off) red[j] = fmaxf(red[j], red[j + off]);
        __syncthreads();
    }
    float mx = red[0];
    __syncthreads();
    float e = (j < CH_) ? expf(val - mx) : 0.f;
    red[j] = e;
    __syncthreads();
    for (int off = 32; off > 0; off >>= 1) {
        if (j < off) red[j] += red[j + off];
        __syncthreads();
    }
    if (j < CH_) g_attn[(size_t)bh * CH_ * CH_ + i * CH_ + j] = e / red[0];
}

// ---------------------------------------------------------------------------
extern "C" void kernel_launch(void* const* d_in, const int* in_sizes, int n_in,
                              void* d_out, int out_size)
{
    const float* x       = (const float*)d_in[0];
    const float* w_qkv   = (const float*)d_in[1];
    const float* w_dw    = (const float*)d_in[2];
    const float* w_proj  = (const float*)d_in[3];
    const float* w_bs_pw = (const float*)d_in[4];
    const float* w_bs_dw = (const float*)d_in[5];

    cudaFuncSetAttribute(gemm_mma_kernel<0>,
                         cudaFuncAttributeMaxDynamicSharedMemorySize, GEMM_SMEM);
    cudaFuncSetAttribute(gemm_mma_kernel<1>,
                         cudaFuncAttributeMaxDynamicSharedMemorySize, GEMM_SMEM);

    // 0) all input converts in one launch (x + weights)
    conv_all_kernel<<<NXB + NWB, 256>>>(x, w_qkv, w_bs_pw, w_proj);
    // 1) fused pointwise GEMM (fp16 HMMA, trans-B, fp16 out)
    gemm_mma_kernel<0><<<dim3(P_ / 128, CT_ / 128, B_), 256, GEMM_SMEM>>>(nullptr);
    // 2) depthwise 3x3 (+GELU on bs channels), 32-row tiles, fused sumsq
    dw_kernel<<<dim3(HH_ / 32, CT_, B_), 256>>>(w_dw, w_bs_dw);
    // 3) attention logits via HMMA (32 split-K partials)
    attn_hmma_kernel<<<dim3(SPLITS_, BH_), 128>>>();
    // 4) softmax with inline norm finalize
    softmax_kernel<<<dim3(CH_, BH_), 64>>>();
    // 5) fuse attn into proj weights: W'1 = Wp1 @ A_blockdiag
    wprime_kernel<<<dim3(BH_, 6), 256>>>(w_proj);
    // 6) projection GEMM (reads V+y from g_dwh directly) -> output fp32
    gemm_mma_kernel<1><<<dim3(P_ / 128, C_ / 128, B_), 256, GEMM_SMEM>>>(d_out);
}

// round 17
// speedup vs baseline: 1.0332x; 1.0332x over previous
#include <cuda_runtime.h>
#include <cuda_fp16.h>
#include <math.h>
#include <stdint.h>

// Problem constants
#define B_    4
#define C_    384
#define C3_   1152
#define CT_   1536        // 1152 qkv + 384 bs
#define HH_   128
#define WW_   128
#define P_    16384       // H*W
#define HEADS_ 8
#define CH_   48
#define BH_   32          // B*HEADS
#define SPLITS_ 32
#define SCALE_ 0.14433756729740643f  // 1/sqrt(48)

#define LDK 40            // padded K stride (halfs) in A smem tiles
#define LDP 136           // padded P stride (halfs) in B smem tiles

// Scratch (static device arrays; no cudaMalloc allowed)
__device__ __align__(256) __half g_pwh[(size_t)B_ * CT_ * P_];  // pointwise out (fp16)
__device__ __align__(256) __half g_dwh[(size_t)B_ * CT_ * P_];  // depthwise out (fp16)
__device__ __align__(256) __half g_xc[(size_t)B_ * C_ * P_];    // x fp16 [b][c][p]
__device__ float g_part[(size_t)BH_ * SPLITS_ * CH_ * CH_];
__device__ float g_npart[(size_t)B_ * 2 * C_ * 4];  // per-block sumsq partials
__device__ float g_attn[(size_t)BH_ * CH_ * CH_];
// fp16 weights
__device__ __align__(256) __half g_wA[(size_t)CT_ * C_];          // [m][k]
__device__ __align__(256) __half g_wPb[(size_t)B_ * C_ * 2 * C_]; // fused proj W per batch

// ---------------------------------------------------------------------------
// Helpers
// ---------------------------------------------------------------------------
__device__ __forceinline__ uint32_t smem_u32(const void* p) {
    uint32_t a;
    asm("{ .reg .u64 t; cvta.to.shared.u64 t, %1; cvt.u32.u64 %0, t; }"
        : "=r"(a) : "l"(p));
    return a;
}
__device__ __forceinline__ void cp16(uint32_t sa, const void* g) {
    asm volatile("cp.async.cg.shared.global [%0], [%1], 16;" :: "r"(sa), "l"(g));
}
#define CP_COMMIT() asm volatile("cp.async.commit_group;" ::: "memory")
#define CP_WAIT0()  asm volatile("cp.async.wait_group 0;" ::: "memory")
#define CP_WAIT1()  asm volatile("cp.async.wait_group 1;" ::: "memory")

__device__ __forceinline__ void ldm_x4(uint32_t* r, uint32_t addr) {
    asm volatile("ldmatrix.sync.aligned.m8n8.x4.shared.b16 {%0,%1,%2,%3}, [%4];"
        : "=r"(r[0]), "=r"(r[1]), "=r"(r[2]), "=r"(r[3]) : "r"(addr));
}
__device__ __forceinline__ void ldm_x4_t(uint32_t* r, uint32_t addr) {
    asm volatile("ldmatrix.sync.aligned.m8n8.x4.trans.shared.b16 {%0,%1,%2,%3}, [%4];"
        : "=r"(r[0]), "=r"(r[1]), "=r"(r[2]), "=r"(r[3]) : "r"(addr));
}
__device__ __forceinline__ void mma16816(float* c, const uint32_t* a, const uint32_t* b) {
    asm volatile("mma.sync.aligned.m16n8k16.row.col.f32.f16.f16.f32 "
        "{%0,%1,%2,%3}, {%4,%5,%6,%7}, {%8,%9}, {%0,%1,%2,%3};"
        : "+f"(c[0]), "+f"(c[1]), "+f"(c[2]), "+f"(c[3])
        : "r"(a[0]), "r"(a[1]), "r"(a[2]), "r"(a[3]), "r"(b[0]), "r"(b[1]));
}

__device__ __forceinline__ uint32_t pack_h(__half a, __half b) {
    return (uint32_t)__half_as_ushort(a) | ((uint32_t)__half_as_ushort(b) << 16);
}

// ---------------------------------------------------------------------------
// Combined convert kernel:
//   blocks [0, NXB)            : x fp32 -> fp16 elementwise (8 per thread)
//   blocks [NXB, NXB+NWB)      : g_wA + y-half of g_wPb weight converts
// ---------------------------------------------------------------------------
#define NXB ((int)(((size_t)B_ * C_ * P_) / (256 * 8)))   // 12288
#define NWB (((CT_ * C_ + C_ * 2 * C_) + 255) / 256)      // 3456

__global__ __launch_bounds__(256) void conv_all_kernel(
    const float* __restrict__ x,
    const float* __restrict__ w_qkv,
    const float* __restrict__ w_bs_pw,
    const float* __restrict__ w_proj)
{
    if (blockIdx.x < NXB) {
        size_t i = ((size_t)blockIdx.x * 256 + threadIdx.x) * 8;
        float4 a = *(const float4*)(x + i);
        float4 c = *(const float4*)(x + i + 4);
        uint4 o;
        o.x = pack_h(__float2half(a.x), __float2half(a.y));
        o.y = pack_h(__float2half(a.z), __float2half(a.w));
        o.z = pack_h(__float2half(c.x), __float2half(c.y));
        o.w = pack_h(__float2half(c.z), __float2half(c.w));
        *(uint4*)(g_xc + i) = o;
    } else {
        const int nA = CT_ * C_;       // 589824
        const int nP = C_ * 2 * C_;    // 294912
        int idx = (blockIdx.x - NXB) * 256 + threadIdx.x;
        if (idx < nA) {
            int m = idx / C_, k = idx % C_;
            float v = (m < C3_) ? w_qkv[m * C_ + k] : w_bs_pw[(m - C3_) * C_ + k];
            g_wA[idx] = __float2half(v);
        } else if (idx < nA + nP) {
            int j = idx - nA;
            int k = j % (2 * C_);
            if (k >= C_) {
                __half hv = __float2half(w_proj[j]);
                #pragma unroll
                for (int b = 0; b < B_; b++)
                    g_wPb[(size_t)b * C_ * 2 * C_ + j] = hv;
            }
        }
    }
}

// ---------------------------------------------------------------------------
// Fused proj weight, attn half: W'[b][m][h*48+d] = sum_d' Wp[m][h*48+d']*A[bh][d'][d]
// grid (BH, 6), 256 threads: each block 64 m-rows x 48 cols
// ---------------------------------------------------------------------------
__global__ __launch_bounds__(256) void wprime_kernel(const float* __restrict__ w_proj)
{
    __shared__ float A[CH_][CH_];
    const int bh = blockIdx.x;
    const int b = bh >> 3, h = bh & 7;
    const int m0 = blockIdx.y * 64;
    const int tid = threadIdx.x;

    for (int i = tid; i < CH_ * CH_; i += 256)
        A[i / CH_][i % CH_] = g_attn[(size_t)bh * CH_ * CH_ + i];
    __syncthreads();

    #pragma unroll
    for (int e = 0; e < 12; e++) {
        int idx = tid + e * 256;           // 0..3071
        int mr = idx / CH_;
        int d  = idx % CH_;
        int m  = m0 + mr;
        const float* wrow = w_proj + (size_t)m * (2 * C_) + h * CH_;
        float s = 0.f;
        #pragma unroll 8
        for (int dp = 0; dp < CH_; dp++)
            s += wrow[dp] * A[dp][d];
        g_wPb[((size_t)b * C_ + m) * (2 * C_) + h * CH_ + d] = __float2half(s);
    }
}

// ---------------------------------------------------------------------------
// HMMA GEMM, pure fp16, B consumed in [k][p] layout via ldmatrix.trans.
// 3-stage cp.async pipeline (wait_group 1).
// MODE 0: pw  (A=g_wA,     B=g_xc,               out g_pwh fp16)
// MODE 1: proj(A=g_wPb[b], B=g_dwh ch 768..1535, out d_out fp32)
// ---------------------------------------------------------------------------
#define ATILE_BYTES (128 * LDK * 2)         // 10240
#define BTILE_BYTES (32 * LDP * 2)          // 8704
#define STAGE_BYTES (ATILE_BYTES + BTILE_BYTES) // 18944
#define GEMM_SMEM (3 * STAGE_BYTES)         // 56832

template <int MODE>
__global__ __launch_bounds__(256) void gemm_mma_kernel(void* __restrict__ outp_v)
{
    extern __shared__ __align__(16) char S[];
    const int Kdim = (MODE == 0) ? C_ : 2 * C_;
    const int Mdim = (MODE == 0) ? CT_ : C_;
    const int b  = blockIdx.z;
    const int n0 = blockIdx.x * 128;
    const int m0 = blockIdx.y * 128;

    const __half* Ap = (MODE == 0) ? g_wA
                                   : g_wPb + (size_t)b * C_ * 2 * C_;
    const __half* Bbase = (MODE == 0)
        ? g_xc + (size_t)b * C_ * P_
        : g_dwh + ((size_t)b * CT_ + 2 * C_) * P_;   // V (384) then y (384)

    const int tid  = threadIdx.x;
    const int lane = tid & 31, warp = tid >> 5;
    const int wm = warp >> 1, wn = warp & 1;
    const uint32_t sbase = smem_u32(S);

    float acc[2][8][4];
    #pragma unroll
    for (int mt = 0; mt < 2; mt++)
        #pragma unroll
        for (int nt = 0; nt < 8; nt++)
            #pragma unroll
            for (int q = 0; q < 4; q++) acc[mt][nt][q] = 0.f;

    const int nch = Kdim / 32;

    // ---- prologue: issue chunks 0 and 1 into stages 0, 1 (one group each)
    #pragma unroll
    for (int pc = 0; pc < 2; pc++) {
        const int k0 = pc * 32;
        const uint32_t stg = sbase + pc * STAGE_BYTES;
        #pragma unroll
        for (int e = 0; e < 4; e++) {
            int idx = tid + e * 256;
            if (idx < 512) {
                int r = idx >> 2, sg = idx & 3;
                uint32_t sa = stg + (r * LDK + sg * 8) * 2;
                cp16(sa, Ap + (size_t)(m0 + r) * Kdim + k0 + sg * 8);
            } else {
                int j2 = idx - 512;
                int r = j2 >> 4, sg = j2 & 15;
                uint32_t sa = stg + ATILE_BYTES + (r * LDP + sg * 8) * 2;
                cp16(sa, Bbase + (size_t)(k0 + r) * P_ + n0 + sg * 8);
            }
        }
        CP_COMMIT();
    }

    for (int c = 0; c < nch; c++) {
        CP_WAIT1();                 // chunk c arrived (one group per chunk)
        __syncthreads();            // all warps done with stage (c+2)%3's old data

        // issue chunk c+2 into stage (c+2)%3; always commit (empty ok)
        if (c + 2 < nch) {
            const int k0 = (c + 2) * 32;
            const uint32_t stg = sbase + ((c + 2) % 3) * STAGE_BYTES;
            #pragma unroll
            for (int e = 0; e < 4; e++) {
                int idx = tid + e * 256;
                if (idx < 512) {
                    int r = idx >> 2, sg = idx & 3;
                    uint32_t sa = stg + (r * LDK + sg * 8) * 2;
                    cp16(sa, Ap + (size_t)(m0 + r) * Kdim + k0 + sg * 8);
                } else {
                    int j2 = idx - 512;
                    int r = j2 >> 4, sg = j2 & 15;
                    uint32_t sa = stg + ATILE_BYTES + (r * LDP + sg * 8) * 2;
                    cp16(sa, Bbase + (size_t)(k0 + r) * P_ + n0 + sg * 8);
                }
            }
        }
        CP_COMMIT();

        // ---- compute on stage c%3
        const uint32_t stb = sbase + (c % 3) * STAGE_BYTES;
        const uint32_t bA = stb;
        const uint32_t bB = stb + ATILE_BYTES;

        #pragma unroll
        for (int kk = 0; kk < 2; kk++) {
            // A (row-major [m][k], non-trans)
            const int kA = kk * 16 + (lane >> 4) * 8;
            const int ar = wm * 32 + (lane & 15);
            uint32_t amat[2][4];
            #pragma unroll
            for (int mt = 0; mt < 2; mt++)
                ldm_x4(amat[mt], bA + ((ar + mt * 16) * LDK + kA) * 2);

            // B ([k][p] layout, trans ldmatrix)
            const int krow = kk * 16 + (lane & 7) + ((lane >> 4) << 3);
            const int ncol = ((lane >> 3) & 1) << 3;
            uint32_t bmat[8][2];
            #pragma unroll
            for (int nt2 = 0; nt2 < 4; nt2++) {
                const int nb = wn * 64 + nt2 * 16;
                uint32_t r[4];
                ldm_x4_t(r, bB + (krow * LDP + nb + ncol) * 2);
                bmat[nt2 * 2][0] = r[0]; bmat[nt2 * 2 + 1][0] = r[1];
                bmat[nt2 * 2][1] = r[2]; bmat[nt2 * 2 + 1][1] = r[3];
            }
            #pragma unroll
            for (int mt = 0; mt < 2; mt++)
                #pragma unroll
                for (int nt = 0; nt < 8; nt++)
                    mma16816(acc[mt][nt], amat[mt], bmat[nt]);
        }
    }

    // ---- epilogue
    if (MODE == 0) {
        __half* outb = g_pwh + (size_t)b * Mdim * P_;
        #pragma unroll
        for (int mt = 0; mt < 2; mt++) {
            int r1 = m0 + wm * 32 + mt * 16 + (lane >> 2);
            #pragma unroll
            for (int nt = 0; nt < 8; nt++) {
                int col = n0 + wn * 64 + nt * 8 + 2 * (lane & 3);
                uint32_t v0 = pack_h(__float2half(acc[mt][nt][0]),
                                     __float2half(acc[mt][nt][1]));
                uint32_t v1 = pack_h(__float2half(acc[mt][nt][2]),
                                     __float2half(acc[mt][nt][3]));
                *(uint32_t*)&outb[(size_t)r1 * P_ + col]       = v0;
                *(uint32_t*)&outb[(size_t)(r1 + 8) * P_ + col] = v1;
            }
        }
    } else {
        float* outb = (float*)outp_v + (size_t)b * Mdim * P_;
        #pragma unroll
        for (int mt = 0; mt < 2; mt++) {
            int r1 = m0 + wm * 32 + mt * 16 + (lane >> 2);
            #pragma unroll
            for (int nt = 0; nt < 8; nt++) {
                int col = n0 + wn * 64 + nt * 8 + 2 * (lane & 3);
                *(float2*)&outb[(size_t)r1 * P_ + col] =
                    make_float2(acc[mt][nt][0], acc[mt][nt][1]);
                *(float2*)&outb[(size_t)(r1 + 8) * P_ + col] =
                    make_float2(acc[mt][nt][2], acc[mt][nt][3]);
            }
        }
    }
}

// ---------------------------------------------------------------------------
// Depthwise 3x3 conv (pad 1) + exact GELU on bs channels.
// fp16 in (uint4 loads) / fp16 out (packed STG.64). 32-row y-tiles (34 halo).
// Each thread: 4-wide x-quad over 2 output rows per half-tile (2 halves).
// Fused q/k sumsq partials. grid (HH/32, CT, B), 256 threads.
// ---------------------------------------------------------------------------
__global__ __launch_bounds__(256) void dw_kernel(
    const float* __restrict__ w_dw,
    const float* __restrict__ w_bs_dw)
{
    __shared__ float s[34][132];
    __shared__ float red[8];
    const int y0 = blockIdx.x * 32;
    const int ch = blockIdx.y;
    const int b  = blockIdx.z;
    const int tid = threadIdx.x;

    const __half* in = g_pwh + ((size_t)b * CT_ + ch) * P_;
    // 34 rows x 16 uint4 (8 halves) = 544 vector loads
    #pragma unroll
    for (int e = 0; e < 3; e++) {
        int idx = tid + e * 256;
        if (idx < 544) {
            int row = idx >> 4;
            int cg  = (idx & 15) * 8;
            int y = y0 - 1 + row;
            float f[8];
            if (y >= 0 && y < HH_) {
                uint4 u = *(const uint4*)(in + y * WW_ + cg);
                const __half2* h2 = (const __half2*)&u;
                #pragma unroll
                for (int q = 0; q < 4; q++) {
                    float2 v = __half22float2(h2[q]);
                    f[2 * q] = v.x; f[2 * q + 1] = v.y;
                }
            } else {
                #pragma unroll
                for (int q = 0; q < 8; q++) f[q] = 0.f;
            }
            #pragma unroll
            for (int q = 0; q < 8; q++) s[row][cg + 1 + q] = f[q];
        }
    }
    if (tid < 68) s[tid >> 1][(tid & 1) * 129] = 0.f;
    __syncthreads();

    const float* wp = (ch < C3_) ? (w_dw + ch * 9) : (w_bs_dw + (ch - C3_) * 9);
    float w[9];
    #pragma unroll
    for (int i = 0; i < 9; i++) w[i] = __ldg(&wp[i]);

    const int x0 = (tid & 31) * 4;     // quad start (phys cols x0..x0+5)
    const int rg = tid >> 5;           // 0..7
    const bool isqk = (ch < 2 * C_);
    const bool isbs = (ch >= C3_);
    __half* outc = g_dwh + ((size_t)b * CT_ + ch) * P_;

    float sumsq = 0.f;
    #pragma unroll
    for (int half = 0; half < 2; half++) {
        const int rb = half * 16 + rg * 2;   // smem top row for this 2-row group

        float rv[4][6];
        #pragma unroll
        for (int r = 0; r < 4; r++) {
            float4 v4 = *(const float4*)&s[rb + r][x0];
            float2 v2 = *(const float2*)&s[rb + r][x0 + 4];
            rv[r][0] = v4.x; rv[r][1] = v4.y; rv[r][2] = v4.z; rv[r][3] = v4.w;
            rv[r][4] = v2.x; rv[r][5] = v2.y;
        }

        #pragma unroll
        for (int j = 0; j < 2; j++) {
            const float* q0 = rv[j];
            const float* q1 = rv[j + 1];
            const float* q2 = rv[j + 2];
            uint32_t ph[2];
            #pragma unroll
            for (int pairi = 0; pairi < 2; pairi++) {
                __half hh[2];
                #pragma unroll
                for (int ii = 0; ii < 2; ii++) {
                    int i = pairi * 2 + ii;
                    float acc = w[0] * q0[i] + w[1] * q0[i + 1] + w[2] * q0[i + 2]
                              + w[3] * q1[i] + w[4] * q1[i + 1] + w[5] * q1[i + 2]
                              + w[6] * q2[i] + w[7] * q2[i + 1] + w[8] * q2[i + 2];
                    if (isbs)
                        acc = 0.5f * acc * (1.0f + erff(acc * 0.70710678118654752f));
                    hh[ii] = __float2half(acc);
                    if (isqk) {
                        float fv = __half2float(hh[ii]);
                        sumsq += fv * fv;
                    }
                }
                ph[pairi] = pack_h(hh[0], hh[1]);
            }
            *(uint2*)&outc[(y0 + rb + j) * WW_ + x0] = make_uint2(ph[0], ph[1]);
        }
    }

    if (isqk) {
        #pragma unroll
        for (int off = 16; off > 0; off >>= 1)
            sumsq += __shfl_xor_sync(0xFFFFFFFFu, sumsq, off);
        if ((tid & 31) == 0) red[tid >> 5] = sumsq;
        __syncthreads();
        if (tid == 0) {
            float t = red[0];
            #pragma unroll
            for (int q = 1; q < 8; q++) t += red[q];
            g_npart[(((size_t)b * 2 * C_ + ch) << 2) + blockIdx.x] = t;
        }
    }
}

// ---------------------------------------------------------------------------
// Attention logits split-K partials via HMMA: S_part = q[48,512] @ k[48,512]^T
// grid (SPLITS=32, BH=32), 128 threads (4 warps, each a K-32 slice per chunk)
// ---------------------------------------------------------------------------
__global__ __launch_bounds__(128) void attn_hmma_kernel()
{
    __shared__ __align__(16) float rbuf[4 * CH_ * CH_];
    __half* qs = (__half*)rbuf;                  // [48][136]
    __half* ks = (__half*)rbuf + 48 * 136;

    const int s  = blockIdx.x;
    const int bh = blockIdx.y;
    const int b = bh >> 3, h = bh & 7;
    const __half* qb = g_dwh + ((size_t)b * CT_ + h * CH_) * P_ + s * 512;
    const __half* kb = g_dwh + ((size_t)b * CT_ + C_ + h * CH_) * P_ + s * 512;

    const int tid = threadIdx.x;
    const int lane = tid & 31, warp = tid >> 5;
    const uint32_t sq = smem_u32(qs), sk = smem_u32(ks);

    float acc[3][6][4];
    #pragma unroll
    for (int mt = 0; mt < 3; mt++)
        #pragma unroll
        for (int nt = 0; nt < 6; nt++)
            #pragma unroll
            for (int q = 0; q < 4; q++) acc[mt][nt][q] = 0.f;

    for (int c0 = 0; c0 < 512; c0 += 128) {
        __syncthreads();
        #pragma unroll
        for (int e = 0; e < 6; e++) {
            int idx = tid + e * 128;       // 0..767
            int row = idx >> 4;
            int cg  = idx & 15;
            *(uint4*)(qs + row * 136 + cg * 8) =
                *(const uint4*)(qb + (size_t)row * P_ + c0 + cg * 8);
            *(uint4*)(ks + row * 136 + cg * 8) =
                *(const uint4*)(kb + (size_t)row * P_ + c0 + cg * 8);
        }
        __syncthreads();

        #pragma unroll
        for (int kk = 0; kk < 2; kk++) {
            const int ko = warp * 32 + kk * 16 + (lane >> 4) * 8;
            uint32_t amat[3][4];
            #pragma unroll
            for (int mt = 0; mt < 3; mt++)
                ldm_x4(amat[mt], sq + ((mt * 16 + (lane & 15)) * 136 + ko) * 2);
            uint32_t bmat[6][2];
            #pragma unroll
            for (int g2 = 0; g2 < 3; g2++) {
                uint32_t r[4];
                ldm_x4(r, sk + ((g2 * 16 + (lane & 15)) * 136 + ko) * 2);
                bmat[g2 * 2][0] = r[0]; bmat[g2 * 2 + 1][0] = r[1];
                bmat[g2 * 2][1] = r[2]; bmat[g2 * 2 + 1][1] = r[3];
            }
            #pragma unroll
            for (int mt = 0; mt < 3; mt++)
                #pragma unroll
                for (int nt = 0; nt < 6; nt++)
                    mma16816(acc[mt][nt], amat[mt], bmat[nt]);
        }
    }
    __syncthreads();

    float* rw = rbuf + warp * (CH_ * CH_);
    #pragma unroll
    for (int mt = 0; mt < 3; mt++)
        #pragma unroll
        for (int nt = 0; nt < 6; nt++) {
            int row = mt * 16 + (lane >> 2);
            int col = nt * 8 + (lane & 3) * 2;
            rw[row * CH_ + col]           = acc[mt][nt][0];
            rw[row * CH_ + col + 1]       = acc[mt][nt][1];
            rw[(row + 8) * CH_ + col]     = acc[mt][nt][2];
            rw[(row + 8) * CH_ + col + 1] = acc[mt][nt][3];
        }
    __syncthreads();

    float* out = g_part + ((size_t)bh * SPLITS_ + s) * (CH_ * CH_);
    for (int i = tid; i < CH_ * CH_; i += 128)
        out[i] = rbuf[i] + rbuf[CH_ * CH_ + i]
               + rbuf[2 * CH_ * CH_ + i] + rbuf[3 * CH_ * CH_ + i];
}

// ---------------------------------------------------------------------------
// Softmax rows; norms computed inline from g_npart partials.
// grid (CH, BH), 64 threads
// ---------------------------------------------------------------------------
__device__ __forceinline__ float norm_of(int b, int ch) {
    const float* p = g_npart + (((size_t)b * 2 * C_ + ch) << 2);
    return fmaxf(sqrtf(p[0] + p[1] + p[2] + p[3]), 1e-12f);
}

__global__ __launch_bounds__(64) void softmax_kernel()
{
    const int i  = blockIdx.x;
    const int bh = blockIdx.y;
    const int b = bh >> 3, h = bh & 7;
    const int j = threadIdx.x;

    float val = 0.f;
    float logit = -1e30f;
    if (j < CH_) {
        float sum = 0.f;
        #pragma unroll
        for (int s = 0; s < SPLITS_; s++)
            sum += g_part[((size_t)bh * SPLITS_ + s) * (CH_ * CH_) + i * CH_ + j];
        float nq = norm_of(b, h * CH_ + i);
        float nk = norm_of(b, C_ + h * CH_ + j);
        val = sum / (nq * nk) * SCALE_;
        logit = val;
    }
    __shared__ float red[64];
    red[j] = logit;
    __syncthreads();
    for (int off = 32; off > 0; off >>= 1) {
        if (j < off) red[j] = fmaxf(red[j], red[j + off]);
        __syncthreads();
    }
    float mx = red[0];
    __syncthreads();
    float e = (j < CH_) ? expf(val - mx) : 0.f;
    red[j] = e;
    __syncthreads();
    for (int off = 32; off > 0; off >>= 1) {
        if (j < off) red[j] += red[j + off];
        __syncthreads();
    }
    if (j < CH_) g_attn[(size_t)bh * CH_ * CH_ + i * CH_ + j] = e / red[0];
}

// ---------------------------------------------------------------------------
extern "C" void kernel_launch(void* const* d_in, const int* in_sizes, int n_in,
                              void* d_out, int out_size)
{
    const float* x       = (const float*)d_in[0];
    const float* w_qkv   = (const float*)d_in[1];
    const float* w_dw    = (const float*)d_in[2];
    const float* w_proj  = (const float*)d_in[3];
    const float* w_bs_pw = (const float*)d_in[4];
    const float* w_bs_dw = (const float*)d_in[5];

    cudaFuncSetAttribute(gemm_mma_kernel<0>,
                         cudaFuncAttributeMaxDynamicSharedMemorySize, GEMM_SMEM);
    cudaFuncSetAttribute(gemm_mma_kernel<1>,
                         cudaFuncAttributeMaxDynamicSharedMemorySize, GEMM_SMEM);

    // 0) all input converts in one launch (x + weights)
    conv_all_kernel<<<NXB + NWB, 256>>>(x, w_qkv, w_bs_pw, w_proj);
    // 1) fused pointwise GEMM (fp16 HMMA, trans-B, 3-stage pipeline)
    gemm_mma_kernel<0><<<dim3(P_ / 128, CT_ / 128, B_), 256, GEMM_SMEM>>>(nullptr);
    // 2) depthwise 3x3 (+GELU on bs channels), 32-row tiles, fused sumsq
    dw_kernel<<<dim3(HH_ / 32, CT_, B_), 256>>>(w_dw, w_bs_dw);
    // 3) attention logits via HMMA (32 split-K partials)
    attn_hmma_kernel<<<dim3(SPLITS_, BH_), 128>>>();
    // 4) softmax with inline norm finalize
    softmax_kernel<<<dim3(CH_, BH_), 64>>>();
    // 5) fuse attn into proj weights: W'1 = Wp1 @ A_blockdiag
    wprime_kernel<<<dim3(BH_, 6), 256>>>(w_proj);
    // 6) projection GEMM (reads V+y from g_dwh directly) -> output fp32
    gemm_mma_kernel<1><<<dim3(P_ / 128, C_ / 128, B_), 256, GEMM_SMEM>>>(d_out);
}